// round 11
// baseline (speedup 1.0000x reference)
#include <cuda_runtime.h>
#include <math.h>

// Shapes (hardcoded from reference setup_inputs)
#define Bn   64
#define Nn   1025
#define Dn   1024
#define Cn   64
#define TOT  (Bn * Nn)   // 65600 rows = 4100 * 16

// Scratch (device globals; no runtime allocation)
__device__ __align__(16) float g_h[(size_t)Bn * Nn * Cn];     // post LN+GEMM1   (B,N,C)
__device__ __align__(16) float g_sp[(size_t)Bn * 1024 * Cn];  // post depthwise  (B,HW,C)
__device__ __align__(16) float g_act[(size_t)Bn * Nn * Cn];   // post proj+gelu  (B,N,C)

// ---------- packed f32x2 helpers ----------
static __device__ __forceinline__ unsigned long long pk2(float a, float b) {
    unsigned long long r;
    asm("mov.b64 %0, {%1,%2};" : "=l"(r) : "f"(a), "f"(b));
    return r;
}
static __device__ __forceinline__ void upk2(unsigned long long v, float& a, float& b) {
    asm("mov.b64 {%0,%1}, %2;" : "=f"(a), "=f"(b) : "l"(v));
}
static __device__ __forceinline__ void fma2(unsigned long long& d, unsigned long long a,
                                            unsigned long long b) {
    asm("fma.rn.f32x2 %0, %1, %2, %0;" : "+l"(d) : "l"(a), "l"(b));
}

static __device__ __forceinline__ float gelu_exact(float t) {
    return 0.5f * t * (1.0f + erff(t * 0.70710678118654752f));
}

// ======================================================================
// Kernel 1: LayerNorm + gamma-mix + GEMM1 (y @ w1 + b1) -> g_h
// 16 rows per block, 512 threads, 1 CTA/SM. Warp-per-row LN (pure shfl),
// single GEMM phase. smem: syd[16][1024] dup ULL (128KB dynamic),
// reused as fp32 reduction buffer. Halves w1 L2 traffic vs 8-row version.
// ======================================================================
#define K1_SMEM (16 * 1024 * 8)

__global__ __launch_bounds__(512, 1) void k1_ln_gemm1(
    const float* __restrict__ x, const float* __restrict__ lnw, const float* __restrict__ lnb,
    const float* __restrict__ gam, const float* __restrict__ gmx,
    const float* __restrict__ w1, const float* __restrict__ b1)
{
    extern __shared__ __align__(16) char sm1[];
    unsigned long long* syd = (unsigned long long*)sm1;   // [16][1024]

    const int tid = threadIdx.x;
    const int warp = tid >> 5, lane = tid & 31;
    const int row0 = blockIdx.x * 16;

    // ---- warp-per-row: load x, stats via shfl, produce y duplicated ----
    {
        const int row = row0 + warp;
        const int rb = row / Nn, rn = row - rb * Nn;
        const float4* xp = (const float4*)(x + ((size_t)(rn * Bn + rb) << 10));
        float4 v[8];
        float s = 0.f, q = 0.f;
#pragma unroll
        for (int i = 0; i < 8; i++) {
            float4 t = xp[lane + 32 * i];
            v[i] = t;
            s += t.x + t.y + t.z + t.w;
            q += t.x * t.x + t.y * t.y + t.z * t.z + t.w * t.w;
        }
#pragma unroll
        for (int o = 16; o; o >>= 1) {
            s += __shfl_xor_sync(0xffffffffu, s, o);
            q += __shfl_xor_sync(0xffffffffu, q, o);
        }
        const float mu = s * (1.0f / 1024.0f);
        const float var = q * (1.0f / 1024.0f) - mu * mu;
        const float rs = rsqrtf(var + 1e-5f);

#pragma unroll
        for (int i = 0; i < 8; i++) {
            const int f4 = lane + 32 * i;
            float4 t = v[i];
            float4 lw = ((const float4*)lnw)[f4];
            float4 lb = ((const float4*)lnb)[f4];
            float4 gm = ((const float4*)gam)[f4];
            float4 gx = ((const float4*)gmx)[f4];
            float y0 = ((t.x - mu) * rs * lw.x + lb.x) * gm.x + t.x * gx.x;
            float y1 = ((t.y - mu) * rs * lw.y + lb.y) * gm.y + t.y * gx.y;
            float y2 = ((t.z - mu) * rs * lw.z + lb.z) * gm.z + t.z * gx.z;
            float y3 = ((t.w - mu) * rs * lw.w + lb.w) * gm.w + t.w * gx.w;
            ulonglong2* dst = (ulonglong2*)(syd + warp * 1024 + f4 * 4);
            ulonglong2 d0; d0.x = pk2(y0, y0); d0.y = pk2(y1, y1);
            ulonglong2 d1; d1.x = pk2(y2, y2); d1.y = pk2(y3, y3);
            dst[0] = d0;
            dst[1] = d1;
        }
    }
    __syncthreads();

    // ---- GEMM: thread = (row-half of 8) x (64-d chunk) x (4 cols) ----
    const int rh = tid >> 8;          // 0/1 -> rows rh*8..+7
    const int t2 = tid & 255;
    const int gidx = t2 >> 4;         // 0..15 -> d in [gidx*64, +64)
    const int cq = t2 & 15;           // cols cq*4..+3
    const int c0 = cq * 4;

    unsigned long long acc[8][2];
#pragma unroll
    for (int r = 0; r < 8; r++) { acc[r][0] = 0ull; acc[r][1] = 0ull; }

    const float4* w1p = (const float4*)w1;
    const unsigned long long* ybase = syd + (size_t)rh * 8 * 1024;
    const int dbase = gidx * 64;
#pragma unroll 4
    for (int dd = 0; dd < 64; dd++) {
        const int d = dbase + dd;
        float4 w = w1p[d * 16 + cq];
        unsigned long long wl = pk2(w.x, w.y), wh = pk2(w.z, w.w);
#pragma unroll
        for (int r = 0; r < 8; r++) {
            unsigned long long yy = ybase[r * 1024 + d];
            fma2(acc[r][0], yy, wl);
            fma2(acc[r][1], yy, wh);
        }
    }
    __syncthreads();

    // ---- cross-kgroup reduction (reuse syd: [16 g][16 r][64 c] floats) ----
    float* red = (float*)syd;
#pragma unroll
    for (int r = 0; r < 8; r++) {
        float a0, a1, a2, a3;
        upk2(acc[r][0], a0, a1);
        upk2(acc[r][1], a2, a3);
        *(float4*)(red + gidx * 1024 + (rh * 8 + r) * 64 + c0) = make_float4(a0, a1, a2, a3);
    }
    __syncthreads();

    {
        const int o = tid * 2;          // 0..1022, pair stays in one row
        const int r = o >> 6, c = o & 63;
        float s0 = 0.f, s1 = 0.f;
#pragma unroll
        for (int g = 0; g < 16; g++) {
            float2 t = *(const float2*)(red + g * 1024 + o);
            s0 += t.x; s1 += t.y;
        }
        float2 bv = *(const float2*)(b1 + c);
        const int row = row0 + r;
        const int rb = row / Nn, rn = row - rb * Nn;
        *(float2*)(g_h + ((size_t)rb * Nn + rn) * 64 + c) = make_float2(s0 + bv.x, s1 + bv.y);
    }
}

// ======================================================================
// Kernel 2: depthwise 3x3 + 5x5 + 7x7, averaged, + identity -> g_sp
// ======================================================================
__global__ __launch_bounds__(256) void k2_dwconv(
    const float* __restrict__ w3, const float* __restrict__ b3,
    const float* __restrict__ w5, const float* __restrict__ b5,
    const float* __restrict__ w7, const float* __restrict__ b7)
{
    __shared__ __align__(16) float tile[38 * 38 * 4];
    __shared__ float wk[4 * 83];

    const int tid = threadIdx.x;
    const int cg = blockIdx.x;
    const int b = blockIdx.y;

    for (int i = tid; i < 4 * 83; i += 256) {
        int ch = i / 83, j = i - ch * 83;
        int c = cg * 4 + ch;
        float wv;
        if (j < 9)       wv = w3[c * 9 + j];
        else if (j < 34) wv = w5[c * 25 + (j - 9)];
        else             wv = w7[c * 49 + (j - 34)];
        wk[i] = wv;
    }

    const float* src = g_h + ((size_t)b * Nn + 1) * 64 + cg * 4;
    for (int idx = tid; idx < 38 * 38; idx += 256) {
        int rr = idx / 38, cc = idx - rr * 38;
        int gy = rr - 3, gx = cc - 3;
        float4 val = make_float4(0.f, 0.f, 0.f, 0.f);
        if ((unsigned)gy < 32u && (unsigned)gx < 32u)
            val = *(const float4*)(src + (size_t)(gy * 32 + gx) * 64);
        *(float4*)&tile[idx * 4] = val;
    }
    __syncthreads();

    const int ch = tid & 3;
    const int col = (tid >> 2) & 31;
    const int row0 = (tid >> 7) * 16;

    float acc[16];
#pragma unroll
    for (int k = 0; k < 16; k++) acc[k] = 0.f;

    const float* wc = wk + ch * 83;

#define CONV_TAPS(RAD, WOFF, KS)                                                   \
    for (int dy = -(RAD); dy <= (RAD); dy++) {                                     \
        for (int dx = -(RAD); dx <= (RAD); dx++) {                                 \
            float wv = wc[(WOFF) + (dy + (RAD)) * (KS) + (dx + (RAD))];            \
            const float* tp = tile + (((row0 + 3 + dy) * 38) + (col + 3 + dx)) * 4 + ch; \
            _Pragma("unroll")                                                      \
            for (int k = 0; k < 16; k++) acc[k] += tp[k * 152] * wv;               \
        }                                                                          \
    }

    CONV_TAPS(1, 0, 3)
    CONV_TAPS(2, 9, 5)
    CONV_TAPS(3, 34, 7)
#undef CONV_TAPS

    const int c = cg * 4 + ch;
    const float bsum = (b3[c] + b5[c] + b7[c]) * (1.0f / 3.0f);
    float* dst = g_sp + ((size_t)b * 1024) * 64 + c;
    const float* ctr = tile + ((row0 + 3) * 38 + col + 3) * 4 + ch;
#pragma unroll
    for (int k = 0; k < 16; k++) {
        float o = acc[k] * (1.0f / 3.0f) + bsum + ctr[k * 152];
        dst[(size_t)((row0 + k) * 32 + col) * 64] = o;
    }
}

// ======================================================================
// Kernel 3: 1x1 proj + residual + exact GELU -> g_act (spatial tokens)
// ======================================================================
__global__ __launch_bounds__(256) void k3_proj_gelu(
    const float* __restrict__ pw, const float* __restrict__ pb)
{
    __shared__ float pws[64 * 65];
    __shared__ float ssp[32 * 64];

    const int tid = threadIdx.x;
    const int b = blockIdx.x >> 5;
    const int pbase = (blockIdx.x & 31) * 32;

    for (int i = tid; i < 4096; i += 256)
        pws[(i >> 6) * 65 + (i & 63)] = pw[i];

    const float* src = g_sp + ((size_t)b * 1024 + pbase) * 64;
    for (int i = tid; i < 2048; i += 256) ssp[i] = src[i];
    __syncthreads();

    const int c = tid & 63;
    const int pg = tid >> 6;
    float acc[8];
#pragma unroll
    for (int j = 0; j < 8; j++) acc[j] = 0.f;

    const float* wr = pws + c * 65;
    const float* sr = ssp + pg * 8 * 64;
#pragma unroll 8
    for (int k = 0; k < 64; k++) {
        float wv = wr[k];
#pragma unroll
        for (int j = 0; j < 8; j++) acc[j] += sr[j * 64 + k] * wv;
    }

    const float pbv = pb[c];
    float* dst = g_act + ((size_t)b * Nn + 1 + pbase + pg * 8) * 64 + c;
#pragma unroll
    for (int j = 0; j < 8; j++) {
        float t = sr[j * 64 + c] + acc[j] + pbv;
        dst[(size_t)j * 64] = gelu_exact(t);
    }
}

// CLS token: gelu only
__global__ void k_cls_gelu() {
    int i = blockIdx.x * 256 + threadIdx.x;
    if (i < Bn * Cn) {
        int b = i >> 6, c = i & 63;
        size_t off = (size_t)b * Nn * 64 + c;
        g_act[off] = gelu_exact(g_h[off]);
    }
}

// ======================================================================
// Kernel 4: GEMM2 (g_act @ w2 + b2) + residual x -> out
// Block = 128-col chunk of w2 resident in smem (32KB, loaded ONCE),
// streams 512 rows in 8 subtiles of 64.
// ======================================================================
#define K4_SMEM (64*128*4 + 64*64*4)

__global__ __launch_bounds__(256, 3) void k4_gemm2(
    const float* __restrict__ x, const float* __restrict__ w2,
    const float* __restrict__ b2, float* __restrict__ out)
{
    extern __shared__ __align__(16) char sm4[];
    float* w2s = (float*)sm4;                      // [64 k][128 c]
    float* sga = (float*)(sm4 + 64 * 128 * 4);     // [64 k][64 r]

    const int tid = threadIdx.x;
    const int rb = blockIdx.x >> 3;
    const int co = (blockIdx.x & 7) * 128;
    const int rowbase = rb * 512;
    const int nsub = (TOT - rowbase < 512) ? ((TOT - rowbase) >> 6) : 8;

#pragma unroll
    for (int i = 0; i < 8; i++) {
        int f = tid + 256 * i;
        int k = f >> 5, c4 = f & 31;
        ((float4*)w2s)[f] = *(const float4*)(w2 + (size_t)k * 1024 + co + c4 * 4);
    }

    const int rg = tid >> 5;
    const int cw = tid & 31;
    const int c0g = co + cw * 4;
    const float4 bv = *(const float4*)(b2 + c0g);

    const int lr = tid >> 2;
    const int lq = tid & 3;

    for (int s2 = 0; s2 < nsub; s2++) {
        __syncthreads();

        {
            int row = rowbase + s2 * 64 + lr;
            int b = row / Nn, n = row - b * Nn;
            const float4* gp = (const float4*)(g_act + ((size_t)b * Nn + n) * 64 + lq * 16);
#pragma unroll
            for (int i = 0; i < 4; i++) {
                float4 g = gp[i];
                int k0 = lq * 16 + i * 4;
                sga[(k0 + 0) * 64 + lr] = g.x;
                sga[(k0 + 1) * 64 + lr] = g.y;
                sga[(k0 + 2) * 64 + lr] = g.z;
                sga[(k0 + 3) * 64 + lr] = g.w;
            }
        }
        __syncthreads();

        unsigned long long acc[4][4];
#pragma unroll
        for (int p = 0; p < 4; p++)
#pragma unroll
            for (int j = 0; j < 4; j++) acc[p][j] = 0ull;

#pragma unroll 4
        for (int k = 0; k < 64; k++) {
            ulonglong2 yA = *(const ulonglong2*)(sga + (k << 6) + (rg << 3));
            ulonglong2 yB = *(const ulonglong2*)(sga + (k << 6) + (rg << 3) + 4);
            float4 w = *(const float4*)(w2s + (k << 7) + (cw << 2));
            unsigned long long w0 = pk2(w.x, w.x), w1d = pk2(w.y, w.y);
            unsigned long long w2d = pk2(w.z, w.z), w3 = pk2(w.w, w.w);
            fma2(acc[0][0], yA.x, w0); fma2(acc[0][1], yA.x, w1d);
            fma2(acc[0][2], yA.x, w2d); fma2(acc[0][3], yA.x, w3);
            fma2(acc[1][0], yA.y, w0); fma2(acc[1][1], yA.y, w1d);
            fma2(acc[1][2], yA.y, w2d); fma2(acc[1][3], yA.y, w3);
            fma2(acc[2][0], yB.x, w0); fma2(acc[2][1], yB.x, w1d);
            fma2(acc[2][2], yB.x, w2d); fma2(acc[2][3], yB.x, w3);
            fma2(acc[3][0], yB.y, w0); fma2(acc[3][1], yB.y, w1d);
            fma2(acc[3][2], yB.y, w2d); fma2(acc[3][3], yB.y, w3);
        }

#pragma unroll
        for (int p = 0; p < 4; p++) {
            int rowe = rowbase + s2 * 64 + rg * 8 + 2 * p;
            float ae[4], ao[4];
#pragma unroll
            for (int j = 0; j < 4; j++) upk2(acc[p][j], ae[j], ao[j]);

            int b = rowe / Nn, n = rowe - b * Nn;
            size_t offe = ((size_t)(n * Bn + b) << 10) + c0g;
            float4 xe = *(const float4*)(x + offe);
            *(float4*)(out + offe) = make_float4(xe.x + bv.x + ae[0], xe.y + bv.y + ae[1],
                                                 xe.z + bv.z + ae[2], xe.w + bv.w + ae[3]);
            int rowo = rowe + 1;
            int b2i = rowo / Nn, n2 = rowo - b2i * Nn;
            size_t offo = ((size_t)(n2 * Bn + b2i) << 10) + c0g;
            float4 xo = *(const float4*)(x + offo);
            *(float4*)(out + offo) = make_float4(xo.x + bv.x + ao[0], xo.y + bv.y + ao[1],
                                                 xo.z + bv.z + ao[2], xo.w + bv.w + ao[3]);
        }
    }
}

// ======================================================================
extern "C" void kernel_launch(void* const* d_in, const int* in_sizes, int n_in,
                              void* d_out, int out_size)
{
    (void)in_sizes; (void)n_in; (void)out_size;
    const float* x     = (const float*)d_in[0];
    const float* ln_w  = (const float*)d_in[1];
    const float* ln_b  = (const float*)d_in[2];
    const float* gamma = (const float*)d_in[3];
    const float* gmx   = (const float*)d_in[4];
    const float* w1    = (const float*)d_in[5];
    const float* b1    = (const float*)d_in[6];
    const float* w2    = (const float*)d_in[7];
    const float* b2    = (const float*)d_in[8];
    const float* dw3w  = (const float*)d_in[9];
    const float* dw3b  = (const float*)d_in[10];
    const float* dw5w  = (const float*)d_in[11];
    const float* dw5b  = (const float*)d_in[12];
    const float* dw7w  = (const float*)d_in[13];
    const float* dw7b  = (const float*)d_in[14];
    const float* projw = (const float*)d_in[15];
    const float* projb = (const float*)d_in[16];
    float* out = (float*)d_out;

    cudaFuncSetAttribute(k1_ln_gemm1, cudaFuncAttributeMaxDynamicSharedMemorySize, K1_SMEM);
    cudaFuncSetAttribute(k4_gemm2,    cudaFuncAttributeMaxDynamicSharedMemorySize, K4_SMEM);

    // 65600 rows = 4100 blocks x 16 rows
    k1_ln_gemm1<<<4100, 512, K1_SMEM>>>(x, ln_w, ln_b, gamma, gmx, w1, b1);
    k2_dwconv<<<dim3(16, 64), 256>>>(dw3w, dw3b, dw5w, dw5b, dw7w, dw7b);
    k_cls_gelu<<<16, 256>>>();
    k3_proj_gelu<<<2048, 256>>>(projw, projb);
    // 129 row-blocks of 512 rows (last has 64) x 8 col-chunks
    k4_gemm2<<<129 * 8, 256, K4_SMEM>>>(x, w2, b2, out);
}